// round 10
// baseline (speedup 1.0000x reference)
#include <cuda_runtime.h>
#include <math.h>

#define V 50257
#define H 1024
#define E 1024
#define L 512
#define HE 2048
#define G3 3072
#define NP 16            // L-partitions for attn-apply (32 rows each)
#define NBLK 3142        // ceil(V/16) = k_logits grid = #LSE partials

// ---------------- scratch (no allocations allowed) ----------------
__device__ float g_attn_logits[L];
__device__ float g_att_part[NP * H];
__device__ float g_x[E];
__device__ float g_gi[G3];
__device__ float g_gh[G3];
__device__ float g_h[H];
__device__ float g_logits[V];
__device__ float g_pmax[NBLK];
__device__ float g_psum[NBLK];

__device__ __forceinline__ float warp_sum(float v) {
    #pragma unroll
    for (int o = 16; o; o >>= 1) v += __shfl_down_sync(0xffffffffu, v, o);
    return v;
}
__device__ __forceinline__ float warp_max(float v) {
    #pragma unroll
    for (int o = 16; o; o >>= 1) v = fmaxf(v, __shfl_down_sync(0xffffffffu, v, o));
    return v;
}
__device__ __forceinline__ float blk_sum(float v, float* s) {
    int lane = threadIdx.x & 31, w = threadIdx.x >> 5;
    v = warp_sum(v);
    if (lane == 0) s[w] = v;
    __syncthreads();
    int nw = (blockDim.x + 31) >> 5;
    v = (threadIdx.x < nw) ? s[threadIdx.x] : 0.0f;
    if (w == 0) v = warp_sum(v);
    __syncthreads();
    return v;
}
__device__ __forceinline__ float blk_max(float v, float* s) {
    int lane = threadIdx.x & 31, w = threadIdx.x >> 5;
    v = warp_max(v);
    if (lane == 0) s[w] = v;
    __syncthreads();
    int nw = (blockDim.x + 31) >> 5;
    v = (threadIdx.x < nw) ? s[threadIdx.x] : -INFINITY;
    if (w == 0) v = warp_max(v);
    __syncthreads();
    return v;
}
__device__ __forceinline__ float sigmoidf_(float x) { return 1.0f / (1.0f + expf(-x)); }

#define DOT4(a, b) ((a).x * (b).x + (a).y * (b).y + (a).z * (b).z + (a).w * (b).w)

// ---------------- 1) stage1: attn logits (blocks 0..63) + gh = h0@w_hh.T (blocks 64..255) ----
// attn: warp-per-row (2048 elems), 16 float4/lane in flight. 64 blocks x 8 rows.
// gh:   2 rows/warp (1024 elems each), 8+8 float4/lane in flight. 192 blocks x 16 rows.
__global__ void k_stage1(const int* __restrict__ tok, const float* __restrict__ hidden,
                         const float* __restrict__ embedding,
                         const float* __restrict__ attn_w, const float* __restrict__ attn_b,
                         const float* __restrict__ w_hh, const float* __restrict__ b_hh) {
    __shared__ float4 sx[HE / 4];   // 8 KB
    const int tid = threadIdx.x, warp = tid >> 5, lane = tid & 31;

    if (blockIdx.x < 64) {
        {
            const float* emb = embedding + (size_t)tok[0] * E;
            sx[tid]       = *(const float4*)(emb + tid * 4);
            sx[tid + 256] = *(const float4*)(hidden + tid * 4);
        }
        __syncthreads();
        const int row = blockIdx.x * 8 + warp;
        const float4* wr = (const float4*)(attn_w + (size_t)row * HE);
        float4 w[16];
        #pragma unroll
        for (int k = 0; k < 16; k++) w[k] = wr[lane + 32 * k];
        float acc = 0.0f;
        #pragma unroll
        for (int k = 0; k < 16; k++) { float4 x4 = sx[lane + 32 * k]; acc += DOT4(w[k], x4); }
        acc = warp_sum(acc);
        if (lane == 0) g_attn_logits[row] = acc + attn_b[row];
    } else {
        sx[tid] = *(const float4*)(hidden + (tid & 255) * 4);   // first 256 slots = h0
        __syncthreads();
        const int b = blockIdx.x - 64;           // 0..191
        const int r0 = b * 16 + warp * 2;
        const float4* w0 = (const float4*)(w_hh + (size_t)r0 * H);
        const float4* w1 = (const float4*)(w_hh + (size_t)(r0 + 1) * H);
        float4 a[8], c[8];
        #pragma unroll
        for (int k = 0; k < 8; k++) a[k] = w0[lane + 32 * k];
        #pragma unroll
        for (int k = 0; k < 8; k++) c[k] = w1[lane + 32 * k];
        float acc0 = 0.0f, acc1 = 0.0f;
        #pragma unroll
        for (int k = 0; k < 8; k++) {
            float4 h4 = sx[lane + 32 * k];
            acc0 += DOT4(a[k], h4);
            acc1 += DOT4(c[k], h4);
        }
        acc0 = warp_sum(acc0);
        acc1 = warp_sum(acc1);
        if (lane == 0) {
            g_gh[r0]     = acc0 + b_hh[r0];
            g_gh[r0 + 1] = acc1 + b_hh[r0 + 1];
        }
    }
}

// ---------------- 2) attn partials with FUSED softmax: grid (H/256, NP) = 64 blocks ----------------
__global__ void k_attnapply(const float* __restrict__ enc, float* __restrict__ out_aw) {
    __shared__ float s[32];
    __shared__ float sl[L];
    __shared__ float aw[32];
    __shared__ float bm, bs;
    const int tid = threadIdx.x;
    sl[tid]       = g_attn_logits[tid];
    sl[tid + 256] = g_attn_logits[tid + 256];
    __syncthreads();
    float m = fmaxf(sl[tid], sl[tid + 256]);
    m = blk_max(m, s);
    if (tid == 0) bm = m;
    __syncthreads();
    float e = expf(sl[tid] - bm) + expf(sl[tid + 256] - bm);
    float sum = blk_sum(e, s);
    if (tid == 0) bs = sum;
    __syncthreads();
    const int r0 = blockIdx.y * 32;
    if (tid < 32) {
        float wv = expf(sl[r0 + tid] - bm) / bs;
        aw[tid] = wv;
        if (blockIdx.x == 0) out_aw[r0 + tid] = wv;
    }
    __syncthreads();
    const int col = blockIdx.x * blockDim.x + tid;
    float acc = 0.0f;
    #pragma unroll 8
    for (int l = 0; l < 32; l++) acc += aw[l] * enc[(size_t)(r0 + l) * H + col];
    g_att_part[blockIdx.y * H + col] = acc;
}

// ---------------- 3) x = relu([emb, att] @ comb_w.T + b): warp-per-row, 16 f4 in flight ----------------
// grid = E/8 = 128 blocks.
__global__ void k_comb(const int* __restrict__ tok, const float* __restrict__ embedding,
                       const float* __restrict__ comb_w, const float* __restrict__ comb_b) {
    __shared__ float4 sx[HE / 4];
    const int tid = threadIdx.x, warp = tid >> 5, lane = tid & 31;
    {
        const float* emb = embedding + (size_t)tok[0] * E;
        sx[tid] = *(const float4*)(emb + tid * 4);
        float4 a = make_float4(0.f, 0.f, 0.f, 0.f);
        #pragma unroll
        for (int p = 0; p < NP; p++) {
            float4 t = *(const float4*)(&g_att_part[p * H + tid * 4]);
            a.x += t.x; a.y += t.y; a.z += t.z; a.w += t.w;
        }
        sx[tid + 256] = a;
    }
    __syncthreads();
    const int row = blockIdx.x * 8 + warp;
    const float4* wr = (const float4*)(comb_w + (size_t)row * HE);
    float4 w[16];
    #pragma unroll
    for (int k = 0; k < 16; k++) w[k] = wr[lane + 32 * k];
    float acc = 0.0f;
    #pragma unroll
    for (int k = 0; k < 16; k++) { float4 x4 = sx[lane + 32 * k]; acc += DOT4(w[k], x4); }
    acc = warp_sum(acc);
    if (lane == 0) g_x[row] = fmaxf(acc + comb_b[row], 0.0f);
}

// ---------------- 4) gi = x @ w_ih.T + b_ih: 2 rows/warp, 16 f4 in flight, grid 192 ----------------
__global__ void k_gru_i(const float* __restrict__ w_ih, const float* __restrict__ b_ih) {
    __shared__ float4 sxv[H / 4];
    const int tid = threadIdx.x, warp = tid >> 5, lane = tid & 31;
    sxv[tid] = *(const float4*)(&g_x[tid * 4]);
    __syncthreads();
    const int r0 = blockIdx.x * 16 + warp * 2;
    const float4* w0 = (const float4*)(w_ih + (size_t)r0 * H);
    const float4* w1 = (const float4*)(w_ih + (size_t)(r0 + 1) * H);
    float4 a[8], c[8];
    #pragma unroll
    for (int k = 0; k < 8; k++) a[k] = w0[lane + 32 * k];
    #pragma unroll
    for (int k = 0; k < 8; k++) c[k] = w1[lane + 32 * k];
    float acc0 = 0.0f, acc1 = 0.0f;
    #pragma unroll
    for (int k = 0; k < 8; k++) {
        float4 x4 = sxv[lane + 32 * k];
        acc0 += DOT4(a[k], x4);
        acc1 += DOT4(c[k], x4);
    }
    acc0 = warp_sum(acc0);
    acc1 = warp_sum(acc1);
    if (lane == 0) {
        g_gi[r0]     = acc0 + b_ih[r0];
        g_gi[r0 + 1] = acc1 + b_ih[r0 + 1];
    }
}

// ---------------- 5) GRU gate combine -> h_new ----------------
__global__ void k_hnew(const float* __restrict__ hidden, float* __restrict__ out_h) {
    const int j = blockIdx.x * blockDim.x + threadIdx.x;
    float r = sigmoidf_(g_gi[j]         + g_gh[j]);
    float z = sigmoidf_(g_gi[H + j]     + g_gh[H + j]);
    float n = tanhf(g_gi[2 * H + j] + r * g_gh[2 * H + j]);
    float h = (1.0f - z) * n + z * hidden[j];
    g_h[j]  = h;
    out_h[j] = h;
}

// ---------------- 6) logits: 2 rows/warp, 16 f4 in flight + FUSED partial-LSE epilogue ----------------
// grid = NBLK = 3142 blocks; block b owns rows [16b, 16b+16) and writes pmax[b], psum[b].
__global__ void k_logits(const float* __restrict__ out_w, const float* __restrict__ out_b) {
    __shared__ float4 shv[H / 4];
    __shared__ float slog[16];
    const int tid = threadIdx.x;
    shv[tid] = *(const float4*)(&g_h[tid * 4]);
    __syncthreads();
    const int warp = tid >> 5, lane = tid & 31;
    int r0 = blockIdx.x * 16 + warp * 2;
    int r1 = r0 + 1;
    const int c0 = (r0 < V) ? r0 : V - 1;     // clamp (duplicate work on tail, write-guarded)
    const int c1 = (r1 < V) ? r1 : V - 1;
    const float4* w0 = (const float4*)(out_w + (size_t)c0 * H);
    const float4* w1 = (const float4*)(out_w + (size_t)c1 * H);
    float4 a[8], b[8];
    #pragma unroll
    for (int k = 0; k < 8; k++) a[k] = w0[lane + 32 * k];
    #pragma unroll
    for (int k = 0; k < 8; k++) b[k] = w1[lane + 32 * k];
    float acc0 = 0.0f, acc1 = 0.0f;
    #pragma unroll
    for (int k = 0; k < 8; k++) {
        float4 h4 = shv[lane + 32 * k];
        acc0 += DOT4(a[k], h4);
        acc1 += DOT4(b[k], h4);
    }
    acc0 = warp_sum(acc0);
    acc1 = warp_sum(acc1);
    if (lane == 0) {
        float l0 = (r0 < V) ? acc0 + out_b[r0] : -INFINITY;
        float l1 = (r1 < V) ? acc1 + out_b[r1] : -INFINITY;
        if (r0 < V) g_logits[r0] = l0;
        if (r1 < V) g_logits[r1] = l1;
        slog[warp * 2]     = l0;
        slog[warp * 2 + 1] = l1;
    }
    __syncthreads();
    if (warp == 0) {        // partial LSE over this block's 16 logits
        float v = (lane < 16) ? slog[lane] : -INFINITY;
        float m = warp_max(v);
        m = __shfl_sync(0xffffffffu, m, 0);
        float e = (lane < 16) ? expf(slog[lane] - m) : 0.0f;
        float sm = warp_sum(e);
        if (lane == 0) {
            g_pmax[blockIdx.x] = m;
            g_psum[blockIdx.x] = sm;
        }
    }
}

// ---------------- 7) final write: combine NBLK partials + log-softmax ----------------
__global__ void k_out(float* __restrict__ out) {
    __shared__ float s[32];
    __shared__ float sM, sLSE;
    const int tid = threadIdx.x;
    float m = -INFINITY;
    for (int i = tid; i < NBLK; i += 256) m = fmaxf(m, g_pmax[i]);
    m = blk_max(m, s);
    if (tid == 0) sM = m;
    __syncthreads();
    const float M = sM;
    float sum = 0.0f;
    for (int i = tid; i < NBLK; i += 256) sum += g_psum[i] * expf(g_pmax[i] - M);
    sum = blk_sum(sum, s);
    if (tid == 0) sLSE = logf(sum);
    __syncthreads();
    const int v = blockIdx.x * blockDim.x + tid;
    if (v < V) out[v] = g_logits[v] - M - sLSE;
}

// ---------------- launch ----------------
extern "C" void kernel_launch(void* const* d_in, const int* in_sizes, int n_in,
                              void* d_out, int out_size) {
    const int*   tok       = (const int*)  d_in[0];
    const float* hidden    = (const float*)d_in[1];
    const float* enc       = (const float*)d_in[2];
    const float* embedding = (const float*)d_in[3];
    const float* attn_w    = (const float*)d_in[4];
    const float* attn_b    = (const float*)d_in[5];
    const float* comb_w    = (const float*)d_in[6];
    const float* comb_b    = (const float*)d_in[7];
    const float* w_ih      = (const float*)d_in[8];
    const float* w_hh      = (const float*)d_in[9];
    const float* b_ih      = (const float*)d_in[10];
    const float* b_hh      = (const float*)d_in[11];
    const float* out_w     = (const float*)d_in[12];
    const float* out_b     = (const float*)d_in[13];
    float* out = (float*)d_out;

    // output layout: [log_softmax (V)] [h_new (H)] [attn_weights (L)]
    k_stage1   <<<256, 256>>>(tok, hidden, embedding, attn_w, attn_b, w_hh, b_hh);
    k_attnapply<<<dim3(H / 256, NP), 256>>>(enc, out + V + H);
    k_comb     <<<E / 8, 256>>>(tok, embedding, comb_w, comb_b);
    k_gru_i    <<<192, 256>>>(w_ih, b_ih);
    k_hnew     <<<H / 256, 256>>>(hidden, out + V);
    k_logits   <<<NBLK, 256>>>(out_w, out_b);
    k_out      <<<(V + 255) / 256, 256>>>(out);
}

// round 11
// speedup vs baseline: 1.0684x; 1.0684x over previous
#include <cuda_runtime.h>
#include <math.h>

#define V 50257
#define H 1024
#define E 1024
#define L 512
#define HE 2048
#define G3 3072
#define NP 16            // L-partitions for attn-apply (32 rows each)
#define PF_BLOCKS 352    // prefetch blocks: comb_w 128 + w_ih 192 + enc 32 (64KB each)

// ---------------- scratch (no allocations allowed) ----------------
__device__ float g_attn_logits[L];
__device__ float g_att_part[NP * H];
__device__ float g_x[E];
__device__ float g_gi[G3];
__device__ float g_gh[G3];
__device__ float g_h[H];
__device__ float g_logits[V];
__device__ float g_pmax[64];
__device__ float g_psum[64];
__device__ float g_sink;         // prefetch discard target (never actually written)

__device__ __forceinline__ float warp_sum(float v) {
    #pragma unroll
    for (int o = 16; o; o >>= 1) v += __shfl_down_sync(0xffffffffu, v, o);
    return v;
}
__device__ __forceinline__ float warp_max(float v) {
    #pragma unroll
    for (int o = 16; o; o >>= 1) v = fmaxf(v, __shfl_down_sync(0xffffffffu, v, o));
    return v;
}
__device__ __forceinline__ float blk_sum(float v, float* s) {
    int lane = threadIdx.x & 31, w = threadIdx.x >> 5;
    v = warp_sum(v);
    if (lane == 0) s[w] = v;
    __syncthreads();
    int nw = (blockDim.x + 31) >> 5;
    v = (threadIdx.x < nw) ? s[threadIdx.x] : 0.0f;
    if (w == 0) v = warp_sum(v);
    __syncthreads();
    return v;
}
__device__ __forceinline__ float blk_max(float v, float* s) {
    int lane = threadIdx.x & 31, w = threadIdx.x >> 5;
    v = warp_max(v);
    if (lane == 0) s[w] = v;
    __syncthreads();
    int nw = (blockDim.x + 31) >> 5;
    v = (threadIdx.x < nw) ? s[threadIdx.x] : -INFINITY;
    if (w == 0) v = warp_max(v);
    __syncthreads();
    return v;
}
__device__ __forceinline__ float sigmoidf_(float x) { return 1.0f / (1.0f + expf(-x)); }

#define DOT4(a, b) ((a).x * (b).x + (a).y * (b).y + (a).z * (b).z + (a).w * (b).w)

// ---------------- 1) stage1: attn logits (0..127) + gh (128..895) + L2 PREFETCH (896..1247) ----
__global__ void k_stage1(const int* __restrict__ tok, const float* __restrict__ hidden,
                         const float* __restrict__ embedding,
                         const float* __restrict__ attn_w, const float* __restrict__ attn_b,
                         const float* __restrict__ w_hh, const float* __restrict__ b_hh,
                         const float* __restrict__ comb_w, const float* __restrict__ w_ih,
                         const float* __restrict__ enc) {
    __shared__ float4 sx[HE / 4];   // 8 KB
    __shared__ float part[8];
    const int tid = threadIdx.x, warp = tid >> 5, lane = tid & 31;
    const int local = warp >> 1, half = warp & 1;

    if (blockIdx.x < 128) {
        {
            const float* emb = embedding + (size_t)tok[0] * E;
            sx[tid]       = *(const float4*)(emb + tid * 4);
            sx[tid + 256] = *(const float4*)(hidden + tid * 4);
        }
        __syncthreads();
        const int row = blockIdx.x * 4 + local;
        const float4* wr = (const float4*)(attn_w + (size_t)row * HE);
        float4 w[8];
        #pragma unroll
        for (int k = 0; k < 8; k++) w[k] = wr[half * 256 + lane + 32 * k];
        float acc = 0.0f;
        #pragma unroll
        for (int k = 0; k < 8; k++) { float4 x4 = sx[half * 256 + lane + 32 * k]; acc += DOT4(w[k], x4); }
        acc = warp_sum(acc);
        if (lane == 0) part[warp] = acc;
        __syncthreads();
        if (tid < 4) {
            const int r = blockIdx.x * 4 + tid;
            g_attn_logits[r] = part[2 * tid] + part[2 * tid + 1] + attn_b[r];
        }
    } else if (blockIdx.x < 896) {
        sx[tid & 255] = *(const float4*)(hidden + (tid & 255) * 4);   // 256 f4 = h0
        __syncthreads();
        const int b = blockIdx.x - 128;          // 0..767
        const int row = b * 4 + local;
        const float4* wr = (const float4*)(w_hh + (size_t)row * H);
        float4 w[4];
        #pragma unroll
        for (int k = 0; k < 4; k++) w[k] = wr[half * 128 + lane + 32 * k];
        float acc = 0.0f;
        #pragma unroll
        for (int k = 0; k < 4; k++) { float4 h4 = sx[half * 128 + lane + 32 * k]; acc += DOT4(w[k], h4); }
        acc = warp_sum(acc);
        if (lane == 0) part[warp] = acc;
        __syncthreads();
        if (tid < 4) {
            const int r = b * 4 + tid;
            g_gh[r] = part[2 * tid] + part[2 * tid + 1] + b_hh[r];
        }
    } else {
        // L2 prefetch: 64 KB per block (16 float4 per thread), sum + impossible guarded write.
        const int p = blockIdx.x - 896;          // 0..351
        const float* src;
        if (p < 128)       src = comb_w + (size_t)p * 16384;          // 128*16384 = E*HE
        else if (p < 320)  src = w_ih   + (size_t)(p - 128) * 16384;  // 192*16384 = 3H*H
        else               src = enc    + (size_t)(p - 320) * 16384;  // 32*16384  = L*H
        const float4* s4 = (const float4*)src;
        float4 acc = make_float4(0.f, 0.f, 0.f, 0.f);
        #pragma unroll
        for (int k = 0; k < 16; k++) {
            float4 t = s4[tid + 256 * k];
            acc.x += t.x; acc.y += t.y; acc.z += t.z; acc.w += t.w;
        }
        if (acc.x == 1.0e38f && acc.y == -1.0e38f && acc.z == 1.0e37f) g_sink = acc.w;
    }
}

// ---------------- 2) attn partials with FUSED softmax: grid (H/256, NP) = 64 blocks ----------------
__global__ void k_attnapply(const float* __restrict__ enc, float* __restrict__ out_aw) {
    __shared__ float s[32];
    __shared__ float sl[L];
    __shared__ float aw[32];
    __shared__ float bm, bs;
    const int tid = threadIdx.x;
    sl[tid]       = g_attn_logits[tid];
    sl[tid + 256] = g_attn_logits[tid + 256];
    __syncthreads();
    float m = fmaxf(sl[tid], sl[tid + 256]);
    m = blk_max(m, s);
    if (tid == 0) bm = m;
    __syncthreads();
    float e = expf(sl[tid] - bm) + expf(sl[tid + 256] - bm);
    float sum = blk_sum(e, s);
    if (tid == 0) bs = sum;
    __syncthreads();
    const int r0 = blockIdx.y * 32;
    if (tid < 32) {
        float wv = expf(sl[r0 + tid] - bm) / bs;
        aw[tid] = wv;
        if (blockIdx.x == 0) out_aw[r0 + tid] = wv;
    }
    __syncthreads();
    const int col = blockIdx.x * blockDim.x + tid;
    float acc = 0.0f;
    #pragma unroll 8
    for (int l = 0; l < 32; l++) acc += aw[l] * enc[(size_t)(r0 + l) * H + col];
    g_att_part[blockIdx.y * H + col] = acc;
}

// ---------------- 3) x = relu([emb, att] @ comb_w.T + b): 4 rows/block, 2 warps/row ----------------
// grid = E/4 = 256 blocks. comb_w is L2-resident after stage1 prefetch.
__global__ void k_comb(const int* __restrict__ tok, const float* __restrict__ embedding,
                       const float* __restrict__ comb_w, const float* __restrict__ comb_b) {
    __shared__ float4 sx[HE / 4];
    __shared__ float part[8];
    const int tid = threadIdx.x, warp = tid >> 5, lane = tid & 31;
    {
        const float* emb = embedding + (size_t)tok[0] * E;
        sx[tid] = *(const float4*)(emb + tid * 4);
        float4 a = make_float4(0.f, 0.f, 0.f, 0.f);
        #pragma unroll
        for (int p = 0; p < NP; p++) {
            float4 t = *(const float4*)(&g_att_part[p * H + tid * 4]);
            a.x += t.x; a.y += t.y; a.z += t.z; a.w += t.w;
        }
        sx[tid + 256] = a;
    }
    __syncthreads();
    const int local = warp >> 1, half = warp & 1;
    const int row = blockIdx.x * 4 + local;
    const float4* wr = (const float4*)(comb_w + (size_t)row * HE);
    float4 w[8];
    #pragma unroll
    for (int k = 0; k < 8; k++) w[k] = wr[half * 256 + lane + 32 * k];
    float acc = 0.0f;
    #pragma unroll
    for (int k = 0; k < 8; k++) { float4 x4 = sx[half * 256 + lane + 32 * k]; acc += DOT4(w[k], x4); }
    acc = warp_sum(acc);
    if (lane == 0) part[warp] = acc;
    __syncthreads();
    if (tid < 4) {
        const int r = blockIdx.x * 4 + tid;
        g_x[r] = fmaxf(part[2 * tid] + part[2 * tid + 1] + comb_b[r], 0.0f);
    }
}

// ---------------- 4) gi = x @ w_ih.T + b_ih: 4 rows/block, 2 warps/row, grid 768 ----------------
// w_ih is L2-resident after stage1 prefetch.
__global__ void k_gru_i(const float* __restrict__ w_ih, const float* __restrict__ b_ih) {
    __shared__ float4 sxv[H / 4];
    __shared__ float part[8];
    const int tid = threadIdx.x, warp = tid >> 5, lane = tid & 31;
    sxv[tid] = *(const float4*)(&g_x[tid * 4]);
    __syncthreads();
    const int local = warp >> 1, half = warp & 1;
    const int row = blockIdx.x * 4 + local;
    const float4* wr = (const float4*)(w_ih + (size_t)row * H);
    float4 w[4];
    #pragma unroll
    for (int k = 0; k < 4; k++) w[k] = wr[half * 128 + lane + 32 * k];
    float acc = 0.0f;
    #pragma unroll
    for (int k = 0; k < 4; k++) { float4 x4 = sxv[half * 128 + lane + 32 * k]; acc += DOT4(w[k], x4); }
    acc = warp_sum(acc);
    if (lane == 0) part[warp] = acc;
    __syncthreads();
    if (tid < 4) {
        const int r = blockIdx.x * 4 + tid;
        g_gi[r] = part[2 * tid] + part[2 * tid + 1] + b_ih[r];
    }
}

// ---------------- 5) GRU gate combine -> h_new ----------------
__global__ void k_hnew(const float* __restrict__ hidden, float* __restrict__ out_h) {
    const int j = blockIdx.x * blockDim.x + threadIdx.x;
    float r = sigmoidf_(g_gi[j]         + g_gh[j]);
    float z = sigmoidf_(g_gi[H + j]     + g_gh[H + j]);
    float n = tanhf(g_gi[2 * H + j] + r * g_gh[2 * H + j]);
    float h = (1.0f - z) * n + z * hidden[j];
    g_h[j]  = h;
    out_h[j] = h;
}

// ---------------- 6) logits: 2 rows/warp, 16 loads in flight, grid ceil(V/16)=3142 ----------------
__global__ void k_logits(const float* __restrict__ out_w, const float* __restrict__ out_b) {
    __shared__ float4 shv[H / 4];
    const int tid = threadIdx.x;
    shv[tid] = *(const float4*)(&g_h[tid * 4]);
    __syncthreads();
    const int warp = tid >> 5, lane = tid & 31;
    int r0 = blockIdx.x * 16 + warp * 2;
    int r1 = r0 + 1;
    const int c0 = (r0 < V) ? r0 : V - 1;     // clamp (duplicate work on tail, write-guarded)
    const int c1 = (r1 < V) ? r1 : V - 1;
    const float4* w0 = (const float4*)(out_w + (size_t)c0 * H);
    const float4* w1 = (const float4*)(out_w + (size_t)c1 * H);
    float4 a[8], b[8];
    #pragma unroll
    for (int k = 0; k < 8; k++) a[k] = w0[lane + 32 * k];
    #pragma unroll
    for (int k = 0; k < 8; k++) b[k] = w1[lane + 32 * k];
    float acc0 = 0.0f, acc1 = 0.0f;
    #pragma unroll
    for (int k = 0; k < 8; k++) {
        float4 h4 = shv[lane + 32 * k];
        acc0 += DOT4(a[k], h4);
        acc1 += DOT4(b[k], h4);
    }
    acc0 = warp_sum(acc0);
    acc1 = warp_sum(acc1);
    if (lane == 0) {
        if (r0 < V) g_logits[r0] = acc0 + out_b[r0];
        if (r1 < V) g_logits[r1] = acc1 + out_b[r1];
    }
}

// ---------------- 7) partial log-sum-exp: 64 blocks ----------------
#define LSE_CHUNK 786    // 64*786 = 50304 >= V
__global__ void k_lse1() {
    __shared__ float s[32];
    __shared__ float bm;
    const int b = blockIdx.x;
    const int lo = b * LSE_CHUNK;
    const int hi = min(lo + LSE_CHUNK, V);
    float m = -INFINITY;
    for (int v = lo + threadIdx.x; v < hi; v += blockDim.x) m = fmaxf(m, g_logits[v]);
    m = blk_max(m, s);
    if (threadIdx.x == 0) bm = m;
    __syncthreads();
    float m0 = bm;
    float sum = 0.0f;
    for (int v = lo + threadIdx.x; v < hi; v += blockDim.x) sum += expf(g_logits[v] - m0);
    sum = blk_sum(sum, s);
    if (threadIdx.x == 0) {
        g_pmax[b] = m0;
        g_psum[b] = sum;
    }
}

// ---------------- 8) final log-softmax write with FUSED partial combine ----------------
__global__ void k_out(float* __restrict__ out) {
    __shared__ float sm_, sls;
    const int tid = threadIdx.x;
    if (tid < 32) {
        float m = fmaxf(g_pmax[tid], g_pmax[tid + 32]);
        m = warp_max(m);
        m = __shfl_sync(0xffffffffu, m, 0);
        float s2 = g_psum[tid] * expf(g_pmax[tid] - m)
                 + g_psum[tid + 32] * expf(g_pmax[tid + 32] - m);
        s2 = warp_sum(s2);
        if (tid == 0) { sm_ = m; sls = logf(s2); }
    }
    __syncthreads();
    const int v = blockIdx.x * blockDim.x + tid;
    if (v < V) out[v] = g_logits[v] - sm_ - sls;
}

// ---------------- launch ----------------
extern "C" void kernel_launch(void* const* d_in, const int* in_sizes, int n_in,
                              void* d_out, int out_size) {
    const int*   tok       = (const int*)  d_in[0];
    const float* hidden    = (const float*)d_in[1];
    const float* enc       = (const float*)d_in[2];
    const float* embedding = (const float*)d_in[3];
    const float* attn_w    = (const float*)d_in[4];
    const float* attn_b    = (const float*)d_in[5];
    const float* comb_w    = (const float*)d_in[6];
    const float* comb_b    = (const float*)d_in[7];
    const float* w_ih      = (const float*)d_in[8];
    const float* w_hh      = (const float*)d_in[9];
    const float* b_ih      = (const float*)d_in[10];
    const float* b_hh      = (const float*)d_in[11];
    const float* out_w     = (const float*)d_in[12];
    const float* out_b     = (const float*)d_in[13];
    float* out = (float*)d_out;

    // output layout: [log_softmax (V)] [h_new (H)] [attn_weights (L)]
    k_stage1   <<<896 + PF_BLOCKS, 256>>>(tok, hidden, embedding, attn_w, attn_b,
                                          w_hh, b_hh, comb_w, w_ih, enc);
    k_attnapply<<<dim3(H / 256, NP), 256>>>(enc, out + V + H);
    k_comb     <<<E / 4, 256>>>(tok, embedding, comb_w, comb_b);
    k_gru_i    <<<G3 / 4, 256>>>(w_ih, b_ih);
    k_hnew     <<<H / 256, 256>>>(hidden, out + V);
    k_logits   <<<(V + 15) / 16, 256>>>(out_w, out_b);
    k_lse1     <<<64, 256>>>();
    k_out      <<<(V + 255) / 256, 256>>>(out);
}